// round 8
// baseline (speedup 1.0000x reference)
#include <cuda_runtime.h>
#include <cstdint>

#define DD 32          // embed dim
#define GI_W 96        // 3*DD gate width
#define NSYM 64        // distinct path symbol values

typedef uint32_t u32;

// ---------------------------------------------------------------------------
// Precomputed tables (device globals: no dynamic allocation allowed)
// ---------------------------------------------------------------------------
__device__ float g_GI_ent[NSYM * GI_W];    // W_ih @ all_emb[e] + b_ih (for H1 build)
__device__ float g_H1[NSYM * DD];          // GRU state after step 1 (key b0)
__device__ float g_H2[NSYM * NSYM * DD];   // GRU state after 2 steps, key (b0,b1)
__device__ float2 g_XT[2][NSYM][16];       // tf32-rounded embeddings, A-frag gather
__device__ float4 g_Bfrag[2][12][2][32];   // MMA B fragments [0]=W_hh,[1]=W_ih
__device__ float  g_bias[128];             // [0..63]=b_ih+b_hh (r,z) [64..95]=b_ih(n) [96..127]=b_hh(n)
__device__ float  g_wlr[DD];               // tf32-rounded w_lin

// ---------------------------------------------------------------------------
// TF32 emulation (reference matmuls are TF32 tensor-core GEMMs)
// ---------------------------------------------------------------------------
__device__ __forceinline__ float tf32r(float x) {
    float r;
    asm("cvt.rna.tf32.f32 %0, %1;" : "=f"(r) : "f"(x));
    return r;
}

// MUFU-native activations (abs err ~1e-5, proven negligible vs TF32 floor)
__device__ __forceinline__ float tanh_mufu(float x) {
    float r;
    asm("tanh.approx.f32 %0, %1;" : "=f"(r) : "f"(x));
    return r;
}
__device__ __forceinline__ float sig_mufu(float x) {
    return fmaf(0.5f, tanh_mufu(0.5f * x), 0.5f);
}

// tf32 MMA: D(16x8) += A(16x8) * B(8x8), fp32 accumulate
__device__ __forceinline__ void mma8(float c[4], const u32 a[4], u32 b0, u32 b1) {
    asm volatile(
        "mma.sync.aligned.m16n8k8.row.col.f32.tf32.tf32.f32 "
        "{%0,%1,%2,%3}, {%4,%5,%6,%7}, {%8,%9}, {%0,%1,%2,%3};"
        : "+f"(c[0]), "+f"(c[1]), "+f"(c[2]), "+f"(c[3])
        : "r"(a[0]), "r"(a[1]), "r"(a[2]), "r"(a[3]), "r"(b0), "r"(b1));
}

// ---------------------------------------------------------------------------
// One MMA GRU step on NT m16-tiles (16*NT paths per warp). Each B-fragment
// smem load is shared by all NT tiles — the per-path LSU traffic divides by NT.
// ---------------------------------------------------------------------------
template<int NT>
__device__ __forceinline__ void gru_step_mma(
        float (*h_c)[4][4], const float2* __restrict__ xt,
        const int* __restrict__ sym0, const int* __restrict__ sym1,
        const float4 (*sB)[12][2][32], const float* __restrict__ sBias,
        int lane, int m, int s0, int s1, bool esel) {
    // Build A fragments for each tile
    u32 Ah[NT][4][4], Ax[NT][4][4];
    #pragma unroll
    for (int tt = 0; tt < NT; tt++) {
        #pragma unroll
        for (int kt = 0; kt < 4; kt++) {
            float v0 = __shfl_sync(0xffffffffu, h_c[tt][kt][0], s0);
            float v1 = __shfl_sync(0xffffffffu, h_c[tt][kt][1], s0);
            float v2 = __shfl_sync(0xffffffffu, h_c[tt][kt][2], s0);
            float v3 = __shfl_sync(0xffffffffu, h_c[tt][kt][3], s0);
            float w0 = __shfl_sync(0xffffffffu, h_c[tt][kt][0], s1);
            float w1 = __shfl_sync(0xffffffffu, h_c[tt][kt][1], s1);
            float w2 = __shfl_sync(0xffffffffu, h_c[tt][kt][2], s1);
            float w3 = __shfl_sync(0xffffffffu, h_c[tt][kt][3], s1);
            Ah[tt][kt][0] = __float_as_uint(tf32r(esel ? v1 : v0));
            Ah[tt][kt][1] = __float_as_uint(tf32r(esel ? v3 : v2));
            Ah[tt][kt][2] = __float_as_uint(tf32r(esel ? w1 : w0));
            Ah[tt][kt][3] = __float_as_uint(tf32r(esel ? w3 : w2));
            float2 q0 = __ldg(xt + sym0[tt] * 16 + kt * 4 + m);
            float2 q1 = __ldg(xt + sym1[tt] * 16 + kt * 4 + m);
            Ax[tt][kt][0] = __float_as_uint(q0.x);
            Ax[tt][kt][1] = __float_as_uint(q1.x);
            Ax[tt][kt][2] = __float_as_uint(q0.y);
            Ax[tt][kt][3] = __float_as_uint(q1.y);
        }
    }

    float rn[NT][4][4];

    // --- r gates (B nt 0..3): fused h+x GEMM, fused bias ---
    #pragma unroll
    for (int nt = 0; nt < 4; nt++) {
        float c[NT][4];
        #pragma unroll
        for (int tt = 0; tt < NT; tt++)
            c[tt][0] = c[tt][1] = c[tt][2] = c[tt][3] = 0.0f;
        #pragma unroll
        for (int kp = 0; kp < 2; kp++) {
            float4 bh = sB[0][nt][kp][lane];
            float4 bi = sB[1][nt][kp][lane];
            #pragma unroll
            for (int tt = 0; tt < NT; tt++) {
                mma8(c[tt], Ah[tt][2 * kp + 0], __float_as_uint(bh.x), __float_as_uint(bh.y));
                mma8(c[tt], Ah[tt][2 * kp + 1], __float_as_uint(bh.z), __float_as_uint(bh.w));
                mma8(c[tt], Ax[tt][2 * kp + 0], __float_as_uint(bi.x), __float_as_uint(bi.y));
                mma8(c[tt], Ax[tt][2 * kp + 1], __float_as_uint(bi.z), __float_as_uint(bi.w));
            }
        }
        float2 bb = *(const float2*)&sBias[8 * nt + 2 * m];
        #pragma unroll
        for (int tt = 0; tt < NT; tt++) {
            rn[tt][nt][0] = sig_mufu(c[tt][0] + bb.x);
            rn[tt][nt][1] = sig_mufu(c[tt][1] + bb.y);
            rn[tt][nt][2] = sig_mufu(c[tt][2] + bb.x);
            rn[tt][nt][3] = sig_mufu(c[tt][3] + bb.y);
        }
    }

    // --- n gates (B nt 8..11): n = tanh(i_n + r*h_n), separate h/x GEMMs ---
    #pragma unroll
    for (int nt = 0; nt < 4; nt++) {
        float ch[NT][4], ci[NT][4];
        #pragma unroll
        for (int tt = 0; tt < NT; tt++) {
            ch[tt][0] = ch[tt][1] = ch[tt][2] = ch[tt][3] = 0.0f;
            ci[tt][0] = ci[tt][1] = ci[tt][2] = ci[tt][3] = 0.0f;
        }
        #pragma unroll
        for (int kp = 0; kp < 2; kp++) {
            float4 bh = sB[0][8 + nt][kp][lane];
            float4 bi = sB[1][8 + nt][kp][lane];
            #pragma unroll
            for (int tt = 0; tt < NT; tt++) {
                mma8(ch[tt], Ah[tt][2 * kp + 0], __float_as_uint(bh.x), __float_as_uint(bh.y));
                mma8(ch[tt], Ah[tt][2 * kp + 1], __float_as_uint(bh.z), __float_as_uint(bh.w));
                mma8(ci[tt], Ax[tt][2 * kp + 0], __float_as_uint(bi.x), __float_as_uint(bi.y));
                mma8(ci[tt], Ax[tt][2 * kp + 1], __float_as_uint(bi.z), __float_as_uint(bi.w));
            }
        }
        float2 bi2 = *(const float2*)&sBias[64 + 8 * nt + 2 * m];
        float2 bh2 = *(const float2*)&sBias[96 + 8 * nt + 2 * m];
        #pragma unroll
        for (int tt = 0; tt < NT; tt++) {
            rn[tt][nt][0] = tanh_mufu(fmaf(rn[tt][nt][0], ch[tt][0] + bh2.x, ci[tt][0] + bi2.x));
            rn[tt][nt][1] = tanh_mufu(fmaf(rn[tt][nt][1], ch[tt][1] + bh2.y, ci[tt][1] + bi2.y));
            rn[tt][nt][2] = tanh_mufu(fmaf(rn[tt][nt][2], ch[tt][2] + bh2.x, ci[tt][2] + bi2.x));
            rn[tt][nt][3] = tanh_mufu(fmaf(rn[tt][nt][3], ch[tt][3] + bh2.y, ci[tt][3] + bi2.y));
        }
    }

    // --- z gates (B nt 4..7) + state update h = z*h + (1-z)*n ---
    #pragma unroll
    for (int nt = 0; nt < 4; nt++) {
        float c[NT][4];
        #pragma unroll
        for (int tt = 0; tt < NT; tt++)
            c[tt][0] = c[tt][1] = c[tt][2] = c[tt][3] = 0.0f;
        #pragma unroll
        for (int kp = 0; kp < 2; kp++) {
            float4 bh = sB[0][4 + nt][kp][lane];
            float4 bi = sB[1][4 + nt][kp][lane];
            #pragma unroll
            for (int tt = 0; tt < NT; tt++) {
                mma8(c[tt], Ah[tt][2 * kp + 0], __float_as_uint(bh.x), __float_as_uint(bh.y));
                mma8(c[tt], Ah[tt][2 * kp + 1], __float_as_uint(bh.z), __float_as_uint(bh.w));
                mma8(c[tt], Ax[tt][2 * kp + 0], __float_as_uint(bi.x), __float_as_uint(bi.y));
                mma8(c[tt], Ax[tt][2 * kp + 1], __float_as_uint(bi.z), __float_as_uint(bi.w));
            }
        }
        float2 bb = *(const float2*)&sBias[32 + 8 * nt + 2 * m];
        #pragma unroll
        for (int tt = 0; tt < NT; tt++) {
            float z0 = sig_mufu(c[tt][0] + bb.x);
            float z1 = sig_mufu(c[tt][1] + bb.y);
            float z2 = sig_mufu(c[tt][2] + bb.x);
            float z3 = sig_mufu(c[tt][3] + bb.y);
            h_c[tt][nt][0] = fmaf(z0, h_c[tt][nt][0], (1.0f - z0) * rn[tt][nt][0]);
            h_c[tt][nt][1] = fmaf(z1, h_c[tt][nt][1], (1.0f - z1) * rn[tt][nt][1]);
            h_c[tt][nt][2] = fmaf(z2, h_c[tt][nt][2], (1.0f - z2) * rn[tt][nt][2]);
            h_c[tt][nt][3] = fmaf(z3, h_c[tt][nt][3], (1.0f - z3) * rn[tt][nt][3]);
        }
    }
}

// ---------------------------------------------------------------------------
// K_setup: fused zero + GI(ent) + XT/Bfrag/bias/w_lin prep. One launch.
// ---------------------------------------------------------------------------
__global__ void k_setup(float* out, int out_size,
                        const float* __restrict__ all_emb,
                        const float* __restrict__ edge_emb,
                        const float* __restrict__ w_ih,
                        const float* __restrict__ w_hh,
                        const float* __restrict__ b_ih,
                        const float* __restrict__ b_hh,
                        const float* __restrict__ w_lin) {
    int i = blockIdx.x * blockDim.x + threadIdx.x;
    if (i < 1024) {
        for (int k = i; k < out_size; k += 1024) out[k] = 0.0f;
        return;
    }
    int gi = i - 1024;
    if (gi < 6144) {               // GI ent: TF32 products, fp64 sum
        int row = gi / GI_W, j = gi % GI_W;
        const float* x = all_emb + row * DD;
        const float* w = w_ih + j * DD;
        double acc = 0.0;
        #pragma unroll
        for (int k = 0; k < DD; k++)
            acc += (double)tf32r(__ldg(w + k)) * (double)tf32r(__ldg(x + k));
        acc += (double)__ldg(b_ih + j);
        g_GI_ent[row * GI_W + j] = (float)acc;
        return;
    }
    int xi = i - 7168;
    if (xi >= 0 && xi < 2048) {    // XT fragments
        int tab = xi >> 10, rem = xi & 1023;
        int sym = rem >> 4, idx = rem & 15;
        int kt = idx >> 2, m = idx & 3;
        const float* src = tab ? (edge_emb + sym * DD) : (all_emb + sym * DD);
        g_XT[tab][sym][idx] = make_float2(tf32r(src[8 * kt + m]),
                                          tf32r(src[8 * kt + m + 4]));
        return;
    }
    int j = i - 9216;
    if (j >= 0 && j < 1536) {      // B fragments
        int lane = j & 31;
        int r1 = j >> 5;
        int kp = r1 & 1;
        int r2 = r1 >> 1;
        int nt = r2 % 12, mat = r2 / 12;
        const float* W = mat ? w_ih : w_hh;
        int row = 8 * nt + (lane >> 2);
        int k0 = 16 * kp + (lane & 3);
        g_Bfrag[mat][nt][kp][lane] = make_float4(
            tf32r(W[row * DD + k0]),     tf32r(W[row * DD + k0 + 4]),
            tf32r(W[row * DD + k0 + 8]), tf32r(W[row * DD + k0 + 12]));
        return;
    }
    int k = i - 10752;
    if (k >= 0 && k < 128) {       // biases
        float v;
        if (k < 64)      v = b_ih[k] + b_hh[k];
        else if (k < 96) v = b_ih[k];
        else             v = b_hh[k - 32];
        g_bias[k] = v;
        return;
    }
    int w = i - 10880;
    if (w >= 0 && w < DD) g_wlr[w] = tf32r(w_lin[w]);
}

// ---------------------------------------------------------------------------
// K_h1: step 1 from h0=0 — depends only on b0 (elementwise)
// ---------------------------------------------------------------------------
__global__ void k_h1(const float* __restrict__ b_hh) {
    int i = blockIdx.x * blockDim.x + threadIdx.x;
    if (i >= NSYM * DD) return;
    int e0 = i >> 5, j = i & 31;
    const float* gi = g_GI_ent + e0 * GI_W;
    float r = sig_mufu(gi[j] + __ldg(b_hh + j));
    float z = sig_mufu(gi[32 + j] + __ldg(b_hh + 32 + j));
    float n = tanh_mufu(fmaf(r, __ldg(b_hh + 64 + j), gi[64 + j]));
    g_H1[e0 * DD + j] = (1.0f - z) * n;
}

// ---------------------------------------------------------------------------
// K_h2: H2 table via MMA. One warp = 16 consecutive keys (NT=1).
// ---------------------------------------------------------------------------
__global__ void __launch_bounds__(128) k_h2(int dummy) {
    __shared__ float4 sB[2][12][2][32];
    __shared__ float sBias[128];
    int tid = threadIdx.x;
    {
        const float4* src = &g_Bfrag[0][0][0][0];
        float4* dst = &sB[0][0][0][0];
        for (int i = tid; i < 1536; i += 128) dst[i] = src[i];
        sBias[tid] = g_bias[tid];
    }
    __syncthreads();

    int warp = tid >> 5, lane = tid & 31;
    int m = lane & 3, grp = lane >> 2;
    int s0 = 4 * grp + (m >> 1), s1 = s0 + 2;
    bool esel = (m & 1) != 0;

    int kbase = (blockIdx.x * 4 + warp) * 16;
    int key0 = kbase + grp;
    int key1 = key0 + 8;

    float h_c[1][4][4];
    const float* H0 = g_H1 + (key0 >> 6) * DD;
    const float* H1 = g_H1 + (key1 >> 6) * DD;
    #pragma unroll
    for (int nt = 0; nt < 4; nt++) {
        float2 v0 = *(const float2*)(H0 + 8 * nt + 2 * m);
        float2 v1 = *(const float2*)(H1 + 8 * nt + 2 * m);
        h_c[0][nt][0] = v0.x; h_c[0][nt][1] = v0.y;
        h_c[0][nt][2] = v1.x; h_c[0][nt][3] = v1.y;
    }

    int sym0[1] = {key0 & 63}, sym1[1] = {key1 & 63};
    gru_step_mma<1>(h_c, &g_XT[1][0][0], sym0, sym1, sB, sBias,
                    lane, m, s0, s1, esel);

    float* D0 = g_H2 + key0 * DD;
    float* D1 = g_H2 + key1 * DD;
    #pragma unroll
    for (int nt = 0; nt < 4; nt++) {
        *(float2*)(D0 + 8 * nt + 2 * m) = make_float2(h_c[0][nt][0], h_c[0][nt][1]);
        *(float2*)(D1 + 8 * nt + 2 * m) = make_float2(h_c[0][nt][2], h_c[0][nt][3]);
    }
}

// ---------------------------------------------------------------------------
// K_main: one warp = 32 paths (2 m16 tiles sharing every B-fragment load).
// ---------------------------------------------------------------------------
__global__ void __launch_bounds__(128, 2) k_main(
        const int* __restrict__ path, const int* __restrict__ path_idx,
        const float* __restrict__ b_lin, float* __restrict__ out, int n_paths) {
    __shared__ float4 sB[2][12][2][32];
    __shared__ float sBias[128];
    __shared__ float sWl[DD];

    int tid = threadIdx.x;
    {
        const float4* src = &g_Bfrag[0][0][0][0];
        float4* dst = &sB[0][0][0][0];
        for (int i = tid; i < 1536; i += 128) dst[i] = src[i];
        sBias[tid] = g_bias[tid];
        if (tid < DD) sWl[tid] = g_wlr[tid];
    }
    __syncthreads();

    int warp = tid >> 5, lane = tid & 31;
    int m = lane & 3, grp = lane >> 2;
    int s0 = 4 * grp + (m >> 1), s1 = s0 + 2;
    bool esel = (m & 1) != 0;

    int pbase = (blockIdx.x * 4 + warp) * 32;
    int n1 = n_paths - 1;

    int p0[2], p1[2];
    int sy[2][2][5];                 // [tile][lo/hi][pos]
    float h_c[2][4][4];
    #pragma unroll
    for (int tt = 0; tt < 2; tt++) {
        p0[tt] = pbase + 16 * tt + grp;
        p1[tt] = p0[tt] + 8;
        int pc0 = min(p0[tt], n1), pc1 = min(p1[tt], n1);
        const int* P0 = path + pc0 * 5;
        const int* P1 = path + pc1 * 5;
        #pragma unroll
        for (int q = 0; q < 5; q++) {
            sy[tt][0][q] = __ldg(P0 + q);
            sy[tt][1][q] = __ldg(P1 + q);
        }
        const float* H0 = g_H2 + (sy[tt][0][0] * NSYM + sy[tt][0][1]) * DD;
        const float* H1 = g_H2 + (sy[tt][1][0] * NSYM + sy[tt][1][1]) * DD;
        #pragma unroll
        for (int nt = 0; nt < 4; nt++) {
            float2 v0 = *(const float2*)(H0 + 8 * nt + 2 * m);
            float2 v1 = *(const float2*)(H1 + 8 * nt + 2 * m);
            h_c[tt][nt][0] = v0.x; h_c[tt][nt][1] = v0.y;
            h_c[tt][nt][2] = v1.x; h_c[tt][nt][3] = v1.y;
        }
    }

    #pragma unroll 1
    for (int t = 0; t < 3; t++) {
        const float2* xt = (t == 1) ? &g_XT[1][0][0] : &g_XT[0][0][0];
        int sym0[2] = {sy[0][0][t + 2], sy[1][0][t + 2]};
        int sym1[2] = {sy[0][1][t + 2], sy[1][1][t + 2]};
        gru_step_mma<2>(h_c, xt, sym0, sym1, sB, sBias, lane, m, s0, s1, esel);
    }

    // Head: s = tf32(h) . tf32(w_lin) + b_lin, quad-reduced per tile
    float bl = __ldg(b_lin);
    #pragma unroll
    for (int tt = 0; tt < 2; tt++) {
        float sc0 = 0.0f, sc1 = 0.0f;
        #pragma unroll
        for (int nt = 0; nt < 4; nt++) {
            float2 wl = *(const float2*)&sWl[8 * nt + 2 * m];
            sc0 = fmaf(tf32r(h_c[tt][nt][0]), wl.x, sc0);
            sc0 = fmaf(tf32r(h_c[tt][nt][1]), wl.y, sc0);
            sc1 = fmaf(tf32r(h_c[tt][nt][2]), wl.x, sc1);
            sc1 = fmaf(tf32r(h_c[tt][nt][3]), wl.y, sc1);
        }
        sc0 += __shfl_xor_sync(0xffffffffu, sc0, 1);
        sc0 += __shfl_xor_sync(0xffffffffu, sc0, 2);
        sc1 += __shfl_xor_sync(0xffffffffu, sc1, 1);
        sc1 += __shfl_xor_sync(0xffffffffu, sc1, 2);
        if (m == 0) {
            if (p0[tt] < n_paths) atomicAdd(out + __ldg(path_idx + p0[tt]), sc0 + bl);
            if (p1[tt] < n_paths) atomicAdd(out + __ldg(path_idx + p1[tt]), sc1 + bl);
        }
    }
}

// ---------------------------------------------------------------------------
extern "C" void kernel_launch(void* const* d_in, const int* in_sizes, int n_in,
                              void* d_out, int out_size) {
    // inputs: 0 users, 1 path, 2 path_idx, 3 all_emb, 4 edge_emb, 5 virtual_emb,
    //         6 w_ih, 7 w_hh, 8 b_ih, 9 b_hh, 10 w_lin, 11 b_lin
    const int*   path     = (const int*)d_in[1];
    const int*   path_idx = (const int*)d_in[2];
    const float* all_emb  = (const float*)d_in[3];
    const float* edge_emb = (const float*)d_in[4];
    const float* w_ih     = (const float*)d_in[6];
    const float* w_hh     = (const float*)d_in[7];
    const float* b_ih     = (const float*)d_in[8];
    const float* b_hh     = (const float*)d_in[9];
    const float* w_lin    = (const float*)d_in[10];
    const float* b_lin    = (const float*)d_in[11];
    float* out = (float*)d_out;
    int n_paths = in_sizes[2];

    k_setup<<<43, 256>>>(out, out_size, all_emb, edge_emb, w_ih, w_hh,
                         b_ih, b_hh, w_lin);
    k_h1<<<2, 1024>>>(b_hh);
    k_h2<<<64, 128>>>(0);
    int nblocks = (n_paths + 127) / 128;   // 128 paths per block (4 warps x 32)
    k_main<<<nblocks, 128>>>(path, path_idx, b_lin, out, n_paths);
}

// round 9
// speedup vs baseline: 1.1556x; 1.1556x over previous
#include <cuda_runtime.h>
#include <cstdint>

#define DD 32          // embed dim
#define GI_W 96        // 3*DD gate width
#define NSYM 64        // distinct path symbol values

typedef uint32_t u32;

// ---------------------------------------------------------------------------
// Precomputed tables (device globals: no dynamic allocation allowed)
// ---------------------------------------------------------------------------
// GIT[tab][sym][j]: W_ih @ x_sym + b_ih  (+ b_hh for j<64, i.e. r/z gates)
//   tab 0 = entity (all_emb), tab 1 = relation (edge_emb)
__device__ float g_GIT[2][NSYM][GI_W];
__device__ float g_H1[NSYM * DD];          // GRU state after step 1 (key b0)
__device__ float g_H2[NSYM * NSYM * DD];   // GRU state after 2 steps, key (b0,b1)
__device__ float4 g_Bfrag[12][2][32];      // MMA B fragments of W_hh only
__device__ float  g_bhn[DD];               // b_hh[64..95] (n-gate hidden bias)
__device__ float  g_wlr[DD];               // tf32-rounded w_lin

// ---------------------------------------------------------------------------
// TF32 emulation (reference matmuls are TF32 tensor-core GEMMs)
// ---------------------------------------------------------------------------
__device__ __forceinline__ float tf32r(float x) {
    float r;
    asm("cvt.rna.tf32.f32 %0, %1;" : "=f"(r) : "f"(x));
    return r;
}

// MUFU-native activations (abs err ~1e-5, proven negligible vs TF32 floor)
__device__ __forceinline__ float tanh_mufu(float x) {
    float r;
    asm("tanh.approx.f32 %0, %1;" : "=f"(r) : "f"(x));
    return r;
}
__device__ __forceinline__ float sig_mufu(float x) {
    return fmaf(0.5f, tanh_mufu(0.5f * x), 0.5f);
}

// tf32 MMA: D(16x8) += A(16x8) * B(8x8), fp32 accumulate
__device__ __forceinline__ void mma8(float c[4], const u32 a[4], u32 b0, u32 b1) {
    asm volatile(
        "mma.sync.aligned.m16n8k8.row.col.f32.tf32.tf32.f32 "
        "{%0,%1,%2,%3}, {%4,%5,%6,%7}, {%8,%9}, {%0,%1,%2,%3};"
        : "+f"(c[0]), "+f"(c[1]), "+f"(c[2]), "+f"(c[3])
        : "r"(a[0]), "r"(a[1]), "r"(a[2]), "r"(a[3]), "r"(b0), "r"(b1));
}

// ---------------------------------------------------------------------------
// One MMA GRU step (16 paths per warp). Only the h-side GEMM runs on tensor
// cores; the x-side contribution + biases come preloaded from GIT as the
// C-accumulator initial values (gp0/gp1 = GIT rows of the two path groups).
// ---------------------------------------------------------------------------
__device__ __forceinline__ void gru_step_mma(
        float h_c[4][4], const float* __restrict__ gp0,
        const float* __restrict__ gp1,
        const float4 (*sB)[2][32], const float* __restrict__ sBhn,
        int lane, int m, int s0, int s1, bool esel) {
    // Build A fragments of tf32(h): a0:(grp,c) a1:(grp+8,c) a2:(grp,c+4) a3
    u32 Ah[4][4];
    #pragma unroll
    for (int kt = 0; kt < 4; kt++) {
        float v0 = __shfl_sync(0xffffffffu, h_c[kt][0], s0);
        float v1 = __shfl_sync(0xffffffffu, h_c[kt][1], s0);
        float v2 = __shfl_sync(0xffffffffu, h_c[kt][2], s0);
        float v3 = __shfl_sync(0xffffffffu, h_c[kt][3], s0);
        float w0 = __shfl_sync(0xffffffffu, h_c[kt][0], s1);
        float w1 = __shfl_sync(0xffffffffu, h_c[kt][1], s1);
        float w2 = __shfl_sync(0xffffffffu, h_c[kt][2], s1);
        float w3 = __shfl_sync(0xffffffffu, h_c[kt][3], s1);
        Ah[kt][0] = __float_as_uint(tf32r(esel ? v1 : v0));
        Ah[kt][1] = __float_as_uint(tf32r(esel ? v3 : v2));
        Ah[kt][2] = __float_as_uint(tf32r(esel ? w1 : w0));
        Ah[kt][3] = __float_as_uint(tf32r(esel ? w3 : w2));
    }

    float rn[4][4];

    // --- r gates (cols 0..31, B frags 0..3): c init = gi_r + b_ih + b_hh ---
    #pragma unroll
    for (int nt = 0; nt < 4; nt++) {
        float2 u = __ldg((const float2*)(gp0 + 8 * nt + 2 * m));
        float2 v = __ldg((const float2*)(gp1 + 8 * nt + 2 * m));
        float c[4] = {u.x, u.y, v.x, v.y};
        #pragma unroll
        for (int kp = 0; kp < 2; kp++) {
            float4 bh = sB[nt][kp][lane];
            mma8(c, Ah[2 * kp + 0], __float_as_uint(bh.x), __float_as_uint(bh.y));
            mma8(c, Ah[2 * kp + 1], __float_as_uint(bh.z), __float_as_uint(bh.w));
        }
        rn[nt][0] = sig_mufu(c[0]);
        rn[nt][1] = sig_mufu(c[1]);
        rn[nt][2] = sig_mufu(c[2]);
        rn[nt][3] = sig_mufu(c[3]);
    }

    // --- n gates (cols 64..95, B frags 8..11):
    //     ch init = b_hh_n (broadcast per column), ci = gi_n + b_ih from GIT
    //     n = tanh(r*ch + ci) ---
    #pragma unroll
    for (int nt = 0; nt < 4; nt++) {
        float2 u = __ldg((const float2*)(gp0 + 64 + 8 * nt + 2 * m));
        float2 v = __ldg((const float2*)(gp1 + 64 + 8 * nt + 2 * m));
        float2 bb = *(const float2*)&sBhn[8 * nt + 2 * m];
        float ch[4] = {bb.x, bb.y, bb.x, bb.y};
        #pragma unroll
        for (int kp = 0; kp < 2; kp++) {
            float4 bh = sB[8 + nt][kp][lane];
            mma8(ch, Ah[2 * kp + 0], __float_as_uint(bh.x), __float_as_uint(bh.y));
            mma8(ch, Ah[2 * kp + 1], __float_as_uint(bh.z), __float_as_uint(bh.w));
        }
        rn[nt][0] = tanh_mufu(fmaf(rn[nt][0], ch[0], u.x));
        rn[nt][1] = tanh_mufu(fmaf(rn[nt][1], ch[1], u.y));
        rn[nt][2] = tanh_mufu(fmaf(rn[nt][2], ch[2], v.x));
        rn[nt][3] = tanh_mufu(fmaf(rn[nt][3], ch[3], v.y));
    }

    // --- z gates (cols 32..63, B frags 4..7) + update h = z*h + (1-z)*n ---
    #pragma unroll
    for (int nt = 0; nt < 4; nt++) {
        float2 u = __ldg((const float2*)(gp0 + 32 + 8 * nt + 2 * m));
        float2 v = __ldg((const float2*)(gp1 + 32 + 8 * nt + 2 * m));
        float c[4] = {u.x, u.y, v.x, v.y};
        #pragma unroll
        for (int kp = 0; kp < 2; kp++) {
            float4 bh = sB[4 + nt][kp][lane];
            mma8(c, Ah[2 * kp + 0], __float_as_uint(bh.x), __float_as_uint(bh.y));
            mma8(c, Ah[2 * kp + 1], __float_as_uint(bh.z), __float_as_uint(bh.w));
        }
        float z0 = sig_mufu(c[0]);
        float z1 = sig_mufu(c[1]);
        float z2 = sig_mufu(c[2]);
        float z3 = sig_mufu(c[3]);
        h_c[nt][0] = fmaf(z0, h_c[nt][0], (1.0f - z0) * rn[nt][0]);
        h_c[nt][1] = fmaf(z1, h_c[nt][1], (1.0f - z1) * rn[nt][1]);
        h_c[nt][2] = fmaf(z2, h_c[nt][2], (1.0f - z2) * rn[nt][2]);
        h_c[nt][3] = fmaf(z3, h_c[nt][3], (1.0f - z3) * rn[nt][3]);
    }
}

// ---------------------------------------------------------------------------
// K_setup: fused zero + GIT + Bfrag(W_hh) + b_hh_n + w_lin. One launch.
// segments: [0,1024) zero | [1024,13312) GIT | [13312,14080) Bfrag
//           [14080,14112) bhn | [14112,14144) wl
// ---------------------------------------------------------------------------
__global__ void k_setup(float* out, int out_size,
                        const float* __restrict__ all_emb,
                        const float* __restrict__ edge_emb,
                        const float* __restrict__ w_ih,
                        const float* __restrict__ w_hh,
                        const float* __restrict__ b_ih,
                        const float* __restrict__ b_hh,
                        const float* __restrict__ w_lin) {
    int i = blockIdx.x * blockDim.x + threadIdx.x;
    if (i < 1024) {
        for (int k = i; k < out_size; k += 1024) out[k] = 0.0f;
        return;
    }
    int g = i - 1024;
    if (g < 12288) {               // GIT: TF32 products, fp64 sum, biases folded
        int tab = g / 6144, rem = g % 6144;
        int sym = rem / GI_W, j = rem % GI_W;
        const float* x = tab ? (edge_emb + sym * DD) : (all_emb + sym * DD);
        const float* w = w_ih + j * DD;
        double acc = 0.0;
        #pragma unroll
        for (int k = 0; k < DD; k++)
            acc += (double)tf32r(__ldg(w + k)) * (double)tf32r(__ldg(x + k));
        acc += (double)__ldg(b_ih + j);
        if (j < 64) acc += (double)__ldg(b_hh + j);   // fold b_hh for r/z gates
        g_GIT[tab][sym][j] = (float)acc;
        return;
    }
    int j = i - 13312;
    if (j >= 0 && j < 768) {       // W_hh B fragments
        int lane = j & 31;
        int r1 = j >> 5;           // 0..23
        int kp = r1 & 1;
        int nt = r1 >> 1;          // 0..11
        int row = 8 * nt + (lane >> 2);
        int k0 = 16 * kp + (lane & 3);
        g_Bfrag[nt][kp][lane] = make_float4(
            tf32r(w_hh[row * DD + k0]),     tf32r(w_hh[row * DD + k0 + 4]),
            tf32r(w_hh[row * DD + k0 + 8]), tf32r(w_hh[row * DD + k0 + 12]));
        return;
    }
    int k = i - 14080;
    if (k >= 0 && k < DD) { g_bhn[k] = b_hh[64 + k]; return; }
    int w = i - 14112;
    if (w >= 0 && w < DD) g_wlr[w] = tf32r(w_lin[w]);
}

// ---------------------------------------------------------------------------
// K_h1: step 1 from h0=0 — depends only on b0 (elementwise; biases pre-folded)
// ---------------------------------------------------------------------------
__global__ void k_h1(int dummy) {
    int i = blockIdx.x * blockDim.x + threadIdx.x;
    if (i >= NSYM * DD) return;
    int e0 = i >> 5, j = i & 31;
    const float* git = &g_GIT[0][e0][0];
    float r = sig_mufu(git[j]);             // gi_r + b_ih + b_hh
    float z = sig_mufu(git[32 + j]);        // gi_z + b_ih + b_hh
    float n = tanh_mufu(fmaf(r, g_bhn[j], git[64 + j]));
    g_H1[e0 * DD + j] = (1.0f - z) * n;
}

// ---------------------------------------------------------------------------
// K_h2: H2 table via MMA. One warp = 16 consecutive keys; one GRU step
// from h1[key>>6] with relation symbol key&63.
// ---------------------------------------------------------------------------
__global__ void __launch_bounds__(128) k_h2(int dummy) {
    __shared__ float4 sB[12][2][32];
    __shared__ float sBhn[DD];
    int tid = threadIdx.x;
    {
        const float4* src = &g_Bfrag[0][0][0];
        float4* dst = &sB[0][0][0];
        for (int i = tid; i < 768; i += 128) dst[i] = src[i];
        if (tid < DD) sBhn[tid] = g_bhn[tid];
    }
    __syncthreads();

    int warp = tid >> 5, lane = tid & 31;
    int m = lane & 3, grp = lane >> 2;
    int s0 = 4 * grp + (m >> 1), s1 = s0 + 2;
    bool esel = (m & 1) != 0;

    int kbase = (blockIdx.x * 4 + warp) * 16;
    int key0 = kbase + grp;
    int key1 = key0 + 8;

    float h_c[4][4];
    const float* H0 = g_H1 + (key0 >> 6) * DD;
    const float* H1 = g_H1 + (key1 >> 6) * DD;
    #pragma unroll
    for (int nt = 0; nt < 4; nt++) {
        float2 v0 = *(const float2*)(H0 + 8 * nt + 2 * m);
        float2 v1 = *(const float2*)(H1 + 8 * nt + 2 * m);
        h_c[nt][0] = v0.x; h_c[nt][1] = v0.y;
        h_c[nt][2] = v1.x; h_c[nt][3] = v1.y;
    }

    const float* gp0 = &g_GIT[1][key0 & 63][0];
    const float* gp1 = &g_GIT[1][key1 & 63][0];
    gru_step_mma(h_c, gp0, gp1, sB, sBhn, lane, m, s0, s1, esel);

    float* D0 = g_H2 + key0 * DD;
    float* D1 = g_H2 + key1 * DD;
    #pragma unroll
    for (int nt = 0; nt < 4; nt++) {
        *(float2*)(D0 + 8 * nt + 2 * m) = make_float2(h_c[nt][0], h_c[nt][1]);
        *(float2*)(D1 + 8 * nt + 2 * m) = make_float2(h_c[nt][2], h_c[nt][3]);
    }
}

// ---------------------------------------------------------------------------
// K_main: one warp = 16 paths; load H2, 3 MMA GRU steps, head, atomic sum.
// ---------------------------------------------------------------------------
__global__ void __launch_bounds__(128, 3) k_main(
        const int* __restrict__ path, const int* __restrict__ path_idx,
        const float* __restrict__ b_lin, float* __restrict__ out, int n_paths) {
    __shared__ float4 sB[12][2][32];
    __shared__ float sBhn[DD];
    __shared__ float sWl[DD];

    int tid = threadIdx.x;
    {
        const float4* src = &g_Bfrag[0][0][0];
        float4* dst = &sB[0][0][0];
        for (int i = tid; i < 768; i += 128) dst[i] = src[i];
        if (tid < DD) sBhn[tid] = g_bhn[tid];
        if (tid >= 64 && tid < 64 + DD) sWl[tid - 64] = g_wlr[tid - 64];
    }
    __syncthreads();

    int warp = tid >> 5, lane = tid & 31;
    int m = lane & 3, grp = lane >> 2;
    int s0 = 4 * grp + (m >> 1), s1 = s0 + 2;
    bool esel = (m & 1) != 0;

    int pbase = (blockIdx.x * 4 + warp) * 16;
    int p0 = pbase + grp;
    int p1 = p0 + 8;
    int n1 = n_paths - 1;
    int pc0 = min(p0, n1), pc1 = min(p1, n1);

    const int* P0 = path + pc0 * 5;
    const int* P1 = path + pc1 * 5;
    int b00 = __ldg(P0 + 0), b01 = __ldg(P0 + 1), b02 = __ldg(P0 + 2),
        b03 = __ldg(P0 + 3), b04 = __ldg(P0 + 4);
    int b10 = __ldg(P1 + 0), b11 = __ldg(P1 + 1), b12 = __ldg(P1 + 2),
        b13 = __ldg(P1 + 3), b14 = __ldg(P1 + 4);

    // Load H2 state into C-fragment layout
    float h_c[4][4];
    const float* H0 = g_H2 + (b00 * NSYM + b01) * DD;
    const float* H1 = g_H2 + (b10 * NSYM + b11) * DD;
    #pragma unroll
    for (int nt = 0; nt < 4; nt++) {
        float2 v0 = *(const float2*)(H0 + 8 * nt + 2 * m);
        float2 v1 = *(const float2*)(H1 + 8 * nt + 2 * m);
        h_c[nt][0] = v0.x; h_c[nt][1] = v0.y;
        h_c[nt][2] = v1.x; h_c[nt][3] = v1.y;
    }

    #pragma unroll 1
    for (int t = 0; t < 3; t++) {
        int tab = (t == 1) ? 1 : 0;
        int sym0 = (t == 0) ? b02 : (t == 1) ? b03 : b04;
        int sym1 = (t == 0) ? b12 : (t == 1) ? b13 : b14;
        const float* gp0 = &g_GIT[tab][sym0][0];
        const float* gp1 = &g_GIT[tab][sym1][0];
        gru_step_mma(h_c, gp0, gp1, sB, sBhn, lane, m, s0, s1, esel);
    }

    // Head: s = tf32(h) . tf32(w_lin) + b_lin, quad-reduced
    float sc0 = 0.0f, sc1 = 0.0f;
    #pragma unroll
    for (int nt = 0; nt < 4; nt++) {
        float2 wl = *(const float2*)&sWl[8 * nt + 2 * m];
        sc0 = fmaf(tf32r(h_c[nt][0]), wl.x, sc0);
        sc0 = fmaf(tf32r(h_c[nt][1]), wl.y, sc0);
        sc1 = fmaf(tf32r(h_c[nt][2]), wl.x, sc1);
        sc1 = fmaf(tf32r(h_c[nt][3]), wl.y, sc1);
    }
    sc0 += __shfl_xor_sync(0xffffffffu, sc0, 1);
    sc0 += __shfl_xor_sync(0xffffffffu, sc0, 2);
    sc1 += __shfl_xor_sync(0xffffffffu, sc1, 1);
    sc1 += __shfl_xor_sync(0xffffffffu, sc1, 2);

    float bl = __ldg(b_lin);
    if (m == 0) {
        if (p0 < n_paths) atomicAdd(out + __ldg(path_idx + p0), sc0 + bl);
        if (p1 < n_paths) atomicAdd(out + __ldg(path_idx + p1), sc1 + bl);
    }
}

// ---------------------------------------------------------------------------
extern "C" void kernel_launch(void* const* d_in, const int* in_sizes, int n_in,
                              void* d_out, int out_size) {
    // inputs: 0 users, 1 path, 2 path_idx, 3 all_emb, 4 edge_emb, 5 virtual_emb,
    //         6 w_ih, 7 w_hh, 8 b_ih, 9 b_hh, 10 w_lin, 11 b_lin
    const int*   path     = (const int*)d_in[1];
    const int*   path_idx = (const int*)d_in[2];
    const float* all_emb  = (const float*)d_in[3];
    const float* edge_emb = (const float*)d_in[4];
    const float* w_ih     = (const float*)d_in[6];
    const float* w_hh     = (const float*)d_in[7];
    const float* b_ih     = (const float*)d_in[8];
    const float* b_hh     = (const float*)d_in[9];
    const float* w_lin    = (const float*)d_in[10];
    const float* b_lin    = (const float*)d_in[11];
    float* out = (float*)d_out;
    int n_paths = in_sizes[2];

    k_setup<<<56, 256>>>(out, out_size, all_emb, edge_emb, w_ih, w_hh,
                         b_ih, b_hh, w_lin);
    k_h1<<<2, 1024>>>(0);
    k_h2<<<64, 128>>>(0);
    int nblocks = (n_paths + 63) / 64;   // 64 paths per block (4 warps x 16)
    k_main<<<nblocks, 128>>>(path, path_idx, b_lin, out, n_paths);
}

// round 11
// speedup vs baseline: 1.4110x; 1.2210x over previous
#include <cuda_runtime.h>
#include <cstdint>

#define DD 32          // embed dim
#define GI_W 96        // 3*DD gate width
#define NSYM 64        // distinct path symbol values

typedef uint32_t u32;

// ---------------------------------------------------------------------------
// Precomputed tables (device globals: no dynamic allocation allowed)
// ---------------------------------------------------------------------------
// Plain GIT (for k_h1): W_ih @ x + b_ih (+ b_hh for j<64)
__device__ float g_GIT[2][NSYM][GI_W];
// Lane-major GIT for MMA kernels: gate column j = c*32 + nt*8 + 2*m + e
// (c: 0=r,1=z,2=n) is stored at [tab][sym][m][c*8 + 2*nt + e].
// Chunk c for one lane = slots [8c, 8c+8); nt-pair pp = float4 at 8c + 4*pp.
__device__ float g_GIT3[2][NSYM][4][24];
__device__ float g_H1[NSYM * DD];          // GRU state after step 1 (key b0)
__device__ float g_H2[NSYM * NSYM * DD];   // GRU state after 2 steps, key (b0,b1)
__device__ float4 g_Bfrag[12][2][32];      // MMA B fragments of W_hh only
__device__ float  g_bhn[DD];               // b_hh[64..95] (n-gate hidden bias)
__device__ float  g_wlr[DD];               // tf32-rounded w_lin

// ---------------------------------------------------------------------------
// TF32 emulation (reference matmuls are TF32 tensor-core GEMMs)
// ---------------------------------------------------------------------------
__device__ __forceinline__ float tf32r(float x) {
    float r;
    asm("cvt.rna.tf32.f32 %0, %1;" : "=f"(r) : "f"(x));
    return r;
}

// MUFU-native activations (abs err ~1e-5, proven negligible vs TF32 floor)
__device__ __forceinline__ float tanh_mufu(float x) {
    float r;
    asm("tanh.approx.f32 %0, %1;" : "=f"(r) : "f"(x));
    return r;
}
__device__ __forceinline__ float sig_mufu(float x) {
    return fmaf(0.5f, tanh_mufu(0.5f * x), 0.5f);
}

// tf32 MMA: D(16x8) += A(16x8) * B(8x8), fp32 accumulate
__device__ __forceinline__ void mma8(float c[4], const u32 a[4], u32 b0, u32 b1) {
    asm volatile(
        "mma.sync.aligned.m16n8k8.row.col.f32.tf32.tf32.f32 "
        "{%0,%1,%2,%3}, {%4,%5,%6,%7}, {%8,%9}, {%0,%1,%2,%3};"
        : "+f"(c[0]), "+f"(c[1]), "+f"(c[2]), "+f"(c[3])
        : "r"(a[0]), "r"(a[1]), "r"(a[2]), "r"(a[3]), "r"(b0), "r"(b1));
}

// ---------------------------------------------------------------------------
// One MMA GRU step on NT m16-tiles (16*NT paths/warp). B-fragment smem loads
// are shared by all tiles. gp0/gp1 = per-tile GIT3 lane pointers (include m).
// ---------------------------------------------------------------------------
template<int NT>
__device__ __forceinline__ void gru_step_mma(
        float (*h_c)[4][4],
        const float* const* gp0, const float* const* gp1,
        const float4 (*sB)[2][32], const float* __restrict__ sBhn,
        int lane, int m, int s0, int s1, bool esel) {
    // A fragments of tf32(h)
    u32 Ah[NT][4][4];
    #pragma unroll
    for (int tt = 0; tt < NT; tt++) {
        #pragma unroll
        for (int kt = 0; kt < 4; kt++) {
            float v0 = __shfl_sync(0xffffffffu, h_c[tt][kt][0], s0);
            float v1 = __shfl_sync(0xffffffffu, h_c[tt][kt][1], s0);
            float v2 = __shfl_sync(0xffffffffu, h_c[tt][kt][2], s0);
            float v3 = __shfl_sync(0xffffffffu, h_c[tt][kt][3], s0);
            float w0 = __shfl_sync(0xffffffffu, h_c[tt][kt][0], s1);
            float w1 = __shfl_sync(0xffffffffu, h_c[tt][kt][1], s1);
            float w2 = __shfl_sync(0xffffffffu, h_c[tt][kt][2], s1);
            float w3 = __shfl_sync(0xffffffffu, h_c[tt][kt][3], s1);
            Ah[tt][kt][0] = __float_as_uint(tf32r(esel ? v1 : v0));
            Ah[tt][kt][1] = __float_as_uint(tf32r(esel ? v3 : v2));
            Ah[tt][kt][2] = __float_as_uint(tf32r(esel ? w1 : w0));
            Ah[tt][kt][3] = __float_as_uint(tf32r(esel ? w3 : w2));
        }
    }

    float rn[NT][4][4];   // r, then n in place

    // --- r gates (GIT3 slots 0..7, B frags 0..3): c init = gi_r+b_ih+b_hh ---
    #pragma unroll
    for (int pp = 0; pp < 2; pp++) {
        float ci[NT][2][4];
        #pragma unroll
        for (int tt = 0; tt < NT; tt++) {
            float4 ga = __ldg((const float4*)(gp0[tt] + 4 * pp));
            float4 gb = __ldg((const float4*)(gp1[tt] + 4 * pp));
            ci[tt][0][0] = ga.x; ci[tt][0][1] = ga.y; ci[tt][0][2] = gb.x; ci[tt][0][3] = gb.y;
            ci[tt][1][0] = ga.z; ci[tt][1][1] = ga.w; ci[tt][1][2] = gb.z; ci[tt][1][3] = gb.w;
        }
        #pragma unroll
        for (int ntl = 0; ntl < 2; ntl++) {
            int nt = 2 * pp + ntl;
            float4 b0 = sB[nt][0][lane];
            float4 b1 = sB[nt][1][lane];
            #pragma unroll
            for (int tt = 0; tt < NT; tt++) {
                mma8(ci[tt][ntl], Ah[tt][0], __float_as_uint(b0.x), __float_as_uint(b0.y));
                mma8(ci[tt][ntl], Ah[tt][1], __float_as_uint(b0.z), __float_as_uint(b0.w));
                mma8(ci[tt][ntl], Ah[tt][2], __float_as_uint(b1.x), __float_as_uint(b1.y));
                mma8(ci[tt][ntl], Ah[tt][3], __float_as_uint(b1.z), __float_as_uint(b1.w));
                rn[tt][nt][0] = sig_mufu(ci[tt][ntl][0]);
                rn[tt][nt][1] = sig_mufu(ci[tt][ntl][1]);
                rn[tt][nt][2] = sig_mufu(ci[tt][ntl][2]);
                rn[tt][nt][3] = sig_mufu(ci[tt][ntl][3]);
            }
        }
    }

    // --- n gates (GIT3 slots 16..23, B frags 8..11): n = tanh(r*gh_n + gi_n) ---
    #pragma unroll
    for (int pp = 0; pp < 2; pp++) {
        float gi0[NT][4], gi1[NT][4];
        #pragma unroll
        for (int tt = 0; tt < NT; tt++) {
            float4 ga = __ldg((const float4*)(gp0[tt] + 16 + 4 * pp));
            float4 gb = __ldg((const float4*)(gp1[tt] + 16 + 4 * pp));
            gi0[tt][0] = ga.x; gi0[tt][1] = ga.y; gi0[tt][2] = gb.x; gi0[tt][3] = gb.y;
            gi1[tt][0] = ga.z; gi1[tt][1] = ga.w; gi1[tt][2] = gb.z; gi1[tt][3] = gb.w;
        }
        #pragma unroll
        for (int ntl = 0; ntl < 2; ntl++) {
            int nt = 2 * pp + ntl;
            float2 bb = *(const float2*)&sBhn[8 * nt + 2 * m];
            float4 b0 = sB[8 + nt][0][lane];
            float4 b1 = sB[8 + nt][1][lane];
            #pragma unroll
            for (int tt = 0; tt < NT; tt++) {
                float ch[4] = {bb.x, bb.y, bb.x, bb.y};
                mma8(ch, Ah[tt][0], __float_as_uint(b0.x), __float_as_uint(b0.y));
                mma8(ch, Ah[tt][1], __float_as_uint(b0.z), __float_as_uint(b0.w));
                mma8(ch, Ah[tt][2], __float_as_uint(b1.x), __float_as_uint(b1.y));
                mma8(ch, Ah[tt][3], __float_as_uint(b1.z), __float_as_uint(b1.w));
                const float* gi = ntl ? gi1[tt] : gi0[tt];
                rn[tt][nt][0] = tanh_mufu(fmaf(rn[tt][nt][0], ch[0], gi[0]));
                rn[tt][nt][1] = tanh_mufu(fmaf(rn[tt][nt][1], ch[1], gi[1]));
                rn[tt][nt][2] = tanh_mufu(fmaf(rn[tt][nt][2], ch[2], gi[2]));
                rn[tt][nt][3] = tanh_mufu(fmaf(rn[tt][nt][3], ch[3], gi[3]));
            }
        }
    }

    // --- z gates (GIT3 slots 8..15, B frags 4..7) + update h = n + z*(h-n) ---
    #pragma unroll
    for (int pp = 0; pp < 2; pp++) {
        float ci[NT][2][4];
        #pragma unroll
        for (int tt = 0; tt < NT; tt++) {
            float4 ga = __ldg((const float4*)(gp0[tt] + 8 + 4 * pp));
            float4 gb = __ldg((const float4*)(gp1[tt] + 8 + 4 * pp));
            ci[tt][0][0] = ga.x; ci[tt][0][1] = ga.y; ci[tt][0][2] = gb.x; ci[tt][0][3] = gb.y;
            ci[tt][1][0] = ga.z; ci[tt][1][1] = ga.w; ci[tt][1][2] = gb.z; ci[tt][1][3] = gb.w;
        }
        #pragma unroll
        for (int ntl = 0; ntl < 2; ntl++) {
            int nt = 2 * pp + ntl;
            float4 b0 = sB[4 + nt][0][lane];
            float4 b1 = sB[4 + nt][1][lane];
            #pragma unroll
            for (int tt = 0; tt < NT; tt++) {
                mma8(ci[tt][ntl], Ah[tt][0], __float_as_uint(b0.x), __float_as_uint(b0.y));
                mma8(ci[tt][ntl], Ah[tt][1], __float_as_uint(b0.z), __float_as_uint(b0.w));
                mma8(ci[tt][ntl], Ah[tt][2], __float_as_uint(b1.x), __float_as_uint(b1.y));
                mma8(ci[tt][ntl], Ah[tt][3], __float_as_uint(b1.z), __float_as_uint(b1.w));
                #pragma unroll
                for (int e = 0; e < 4; e++) {
                    float z = sig_mufu(ci[tt][ntl][e]);
                    float n = rn[tt][nt][e];
                    h_c[tt][nt][e] = fmaf(z, h_c[tt][nt][e] - n, n);
                }
            }
        }
    }
}

// ---------------------------------------------------------------------------
// K_setup: fused zero + GIT/GIT3 + Bfrag(W_hh) + b_hh_n + w_lin. One launch.
// ---------------------------------------------------------------------------
__global__ void k_setup(float* out, int out_size,
                        const float* __restrict__ all_emb,
                        const float* __restrict__ edge_emb,
                        const float* __restrict__ w_ih,
                        const float* __restrict__ w_hh,
                        const float* __restrict__ b_ih,
                        const float* __restrict__ b_hh,
                        const float* __restrict__ w_lin) {
    int i = blockIdx.x * blockDim.x + threadIdx.x;
    if (i < 1024) {
        for (int k = i; k < out_size; k += 1024) out[k] = 0.0f;
        return;
    }
    int g = i - 1024;
    if (g < 12288) {               // GIT: TF32 products, fp64 sum, biases folded
        int tab = g / 6144, rem = g % 6144;
        int sym = rem / GI_W, j = rem % GI_W;
        const float* x = tab ? (edge_emb + sym * DD) : (all_emb + sym * DD);
        const float* w = w_ih + j * DD;
        double acc = 0.0;
        #pragma unroll
        for (int k = 0; k < DD; k++)
            acc += (double)tf32r(__ldg(w + k)) * (double)tf32r(__ldg(x + k));
        acc += (double)__ldg(b_ih + j);
        if (j < 64) acc += (double)__ldg(b_hh + j);   // fold b_hh for r/z gates
        float v = (float)acc;
        g_GIT[tab][sym][j] = v;
        // lane-major copy: col j = c*32 + nt*8 + 2*mm + e -> [mm][c*8+2*nt+e]
        int c = j >> 5, r2 = j & 31, nt = r2 >> 3, me = r2 & 7;
        g_GIT3[tab][sym][me >> 1][c * 8 + 2 * nt + (me & 1)] = v;
        return;
    }
    int j = i - 13312;
    if (j >= 0 && j < 768) {       // W_hh B fragments
        int lane = j & 31;
        int r1 = j >> 5;           // 0..23
        int kp = r1 & 1;
        int nt = r1 >> 1;          // 0..11
        int row = 8 * nt + (lane >> 2);
        int k0 = 16 * kp + (lane & 3);
        g_Bfrag[nt][kp][lane] = make_float4(
            tf32r(w_hh[row * DD + k0]),     tf32r(w_hh[row * DD + k0 + 4]),
            tf32r(w_hh[row * DD + k0 + 8]), tf32r(w_hh[row * DD + k0 + 12]));
        return;
    }
    int k = i - 14080;
    if (k >= 0 && k < DD) { g_bhn[k] = b_hh[64 + k]; return; }
    int w = i - 14112;
    if (w >= 0 && w < DD) g_wlr[w] = tf32r(w_lin[w]);
}

// ---------------------------------------------------------------------------
// K_h1: step 1 from h0=0 — depends only on b0 (elementwise; biases pre-folded)
// ---------------------------------------------------------------------------
__global__ void k_h1(int dummy) {
    int i = blockIdx.x * blockDim.x + threadIdx.x;
    if (i >= NSYM * DD) return;
    int e0 = i >> 5, j = i & 31;
    const float* git = &g_GIT[0][e0][0];
    float r = sig_mufu(git[j]);
    float z = sig_mufu(git[32 + j]);
    float n = tanh_mufu(fmaf(r, g_bhn[j], git[64 + j]));
    g_H1[e0 * DD + j] = (1.0f - z) * n;
}

// ---------------------------------------------------------------------------
// K_h2: H2 table via MMA (NT=1). One warp = 16 consecutive keys.
// ---------------------------------------------------------------------------
__global__ void __launch_bounds__(128) k_h2(int dummy) {
    __shared__ float4 sB[12][2][32];
    __shared__ float sBhn[DD];
    int tid = threadIdx.x;
    {
        const float4* src = &g_Bfrag[0][0][0];
        float4* dst = &sB[0][0][0];
        for (int i = tid; i < 768; i += 128) dst[i] = src[i];
        if (tid < DD) sBhn[tid] = g_bhn[tid];
    }
    __syncthreads();

    int warp = tid >> 5, lane = tid & 31;
    int m = lane & 3, grp = lane >> 2;
    int s0 = 4 * grp + (m >> 1), s1 = s0 + 2;
    bool esel = (m & 1) != 0;

    int kbase = (blockIdx.x * 4 + warp) * 16;
    int key0 = kbase + grp;
    int key1 = key0 + 8;

    float h_c[1][4][4];
    const float* H0 = g_H1 + (key0 >> 6) * DD;
    const float* H1 = g_H1 + (key1 >> 6) * DD;
    #pragma unroll
    for (int nt = 0; nt < 4; nt++) {
        float2 v0 = *(const float2*)(H0 + 8 * nt + 2 * m);
        float2 v1 = *(const float2*)(H1 + 8 * nt + 2 * m);
        h_c[0][nt][0] = v0.x; h_c[0][nt][1] = v0.y;
        h_c[0][nt][2] = v1.x; h_c[0][nt][3] = v1.y;
    }

    const float* gp0[1] = { &g_GIT3[1][key0 & 63][m][0] };
    const float* gp1[1] = { &g_GIT3[1][key1 & 63][m][0] };
    gru_step_mma<1>(h_c, gp0, gp1, sB, sBhn, lane, m, s0, s1, esel);

    float* D0 = g_H2 + key0 * DD;
    float* D1 = g_H2 + key1 * DD;
    #pragma unroll
    for (int nt = 0; nt < 4; nt++) {
        *(float2*)(D0 + 8 * nt + 2 * m) = make_float2(h_c[0][nt][0], h_c[0][nt][1]);
        *(float2*)(D1 + 8 * nt + 2 * m) = make_float2(h_c[0][nt][2], h_c[0][nt][3]);
    }
}

// ---------------------------------------------------------------------------
// K_main: one warp = 32 paths (2 m16 tiles share every B-fragment LDS).
// ---------------------------------------------------------------------------
__global__ void __launch_bounds__(128, 3) k_main(
        const int* __restrict__ path, const int* __restrict__ path_idx,
        const float* __restrict__ b_lin, float* __restrict__ out, int n_paths) {
    __shared__ float4 sB[12][2][32];
    __shared__ float sBhn[DD];
    __shared__ float sWl[DD];

    int tid = threadIdx.x;
    {
        const float4* src = &g_Bfrag[0][0][0];
        float4* dst = &sB[0][0][0];
        for (int i = tid; i < 768; i += 128) dst[i] = src[i];
        if (tid < DD) sBhn[tid] = g_bhn[tid];
        if (tid >= 64 && tid < 64 + DD) sWl[tid - 64] = g_wlr[tid - 64];
    }
    __syncthreads();

    int lane = tid & 31;
    int m = lane & 3, grp = lane >> 2;
    int s0 = 4 * grp + (m >> 1), s1 = s0 + 2;
    bool esel = (m & 1) != 0;

    int pbase = (blockIdx.x * 4 + (tid >> 5)) * 32;
    int n1 = n_paths - 1;

    // Load per-tile symbols (packed) and H2 state
    int spk[2][2];                 // [tile][half]: b2 | b3<<8 | b4<<16
    float h_c[2][4][4];
    #pragma unroll
    for (int tt = 0; tt < 2; tt++) {
        #pragma unroll
        for (int hf = 0; hf < 2; hf++) {
            int p = min(pbase + 16 * tt + grp + 8 * hf, n1);
            const int* P = path + p * 5;
            int b0 = __ldg(P + 0), b1 = __ldg(P + 1);
            spk[tt][hf] = __ldg(P + 2) | (__ldg(P + 3) << 8) | (__ldg(P + 4) << 16);
            const float* H = g_H2 + (b0 * NSYM + b1) * DD;
            #pragma unroll
            for (int nt = 0; nt < 4; nt++) {
                float2 v = *(const float2*)(H + 8 * nt + 2 * m);
                h_c[tt][nt][2 * hf + 0] = v.x;
                h_c[tt][nt][2 * hf + 1] = v.y;
            }
        }
    }

    #pragma unroll 1
    for (int t = 0; t < 3; t++) {
        int tab = (t == 1) ? 1 : 0;
        int sh = 8 * t;
        const float* gp0[2] = {
            &g_GIT3[tab][(spk[0][0] >> sh) & 63][m][0],
            &g_GIT3[tab][(spk[1][0] >> sh) & 63][m][0] };
        const float* gp1[2] = {
            &g_GIT3[tab][(spk[0][1] >> sh) & 63][m][0],
            &g_GIT3[tab][(spk[1][1] >> sh) & 63][m][0] };
        gru_step_mma<2>(h_c, gp0, gp1, sB, sBhn, lane, m, s0, s1, esel);
    }

    // Head: s = tf32(h) . tf32(w_lin) + b_lin, quad-reduced per tile
    float bl = __ldg(b_lin);
    #pragma unroll
    for (int tt = 0; tt < 2; tt++) {
        float sc0 = 0.0f, sc1 = 0.0f;
        #pragma unroll
        for (int nt = 0; nt < 4; nt++) {
            float2 wl = *(const float2*)&sWl[8 * nt + 2 * m];
            sc0 = fmaf(tf32r(h_c[tt][nt][0]), wl.x, sc0);
            sc0 = fmaf(tf32r(h_c[tt][nt][1]), wl.y, sc0);
            sc1 = fmaf(tf32r(h_c[tt][nt][2]), wl.x, sc1);
            sc1 = fmaf(tf32r(h_c[tt][nt][3]), wl.y, sc1);
        }
        sc0 += __shfl_xor_sync(0xffffffffu, sc0, 1);
        sc0 += __shfl_xor_sync(0xffffffffu, sc0, 2);
        sc1 += __shfl_xor_sync(0xffffffffu, sc1, 1);
        sc1 += __shfl_xor_sync(0xffffffffu, sc1, 2);
        if (m == 0) {
            int p0 = pbase + 16 * tt + grp;
            int p1 = p0 + 8;
            if (p0 < n_paths) atomicAdd(out + __ldg(path_idx + p0), sc0 + bl);
            if (p1 < n_paths) atomicAdd(out + __ldg(path_idx + p1), sc1 + bl);
        }
    }
}

// ---------------------------------------------------------------------------
extern "C" void kernel_launch(void* const* d_in, const int* in_sizes, int n_in,
                              void* d_out, int out_size) {
    // inputs: 0 users, 1 path, 2 path_idx, 3 all_emb, 4 edge_emb, 5 virtual_emb,
    //         6 w_ih, 7 w_hh, 8 b_ih, 9 b_hh, 10 w_lin, 11 b_lin
    const int*   path     = (const int*)d_in[1];
    const int*   path_idx = (const int*)d_in[2];
    const float* all_emb  = (const float*)d_in[3];
    const float* edge_emb = (const float*)d_in[4];
    const float* w_ih     = (const float*)d_in[6];
    const float* w_hh     = (const float*)d_in[7];
    const float* b_ih     = (const float*)d_in[8];
    const float* b_hh     = (const float*)d_in[9];
    const float* w_lin    = (const float*)d_in[10];
    const float* b_lin    = (const float*)d_in[11];
    float* out = (float*)d_out;
    int n_paths = in_sizes[2];

    k_setup<<<56, 256>>>(out, out_size, all_emb, edge_emb, w_ih, w_hh,
                         b_ih, b_hh, w_lin);
    k_h1<<<2, 1024>>>(0);
    k_h2<<<64, 128>>>(0);
    int nblocks = (n_paths + 127) / 128;   // 128 paths per block (4 warps x 32)
    k_main<<<nblocks, 128>>>(path, path_idx, b_lin, out, n_paths);
}

// round 12
// speedup vs baseline: 1.5264x; 1.0817x over previous
#include <cuda_runtime.h>
#include <cstdint>

#define DD 32          // embed dim
#define GI_W 96        // 3*DD gate width
#define NSYM 64        // distinct path symbol values

typedef uint32_t u32;

// ---------------------------------------------------------------------------
// Precomputed tables (device globals: no dynamic allocation allowed)
// ---------------------------------------------------------------------------
// Plain GIT (for k_h1): W_ih @ x + b_ih (+ b_hh for j<64)
__device__ float g_GIT[2][NSYM][GI_W];
// Slot-major GIT for MMA kernels: [tab][sym][slot][m], slot = 2c+pp
// (c: 0=r,1=z,2=n). float4 [slot][m] holds gate cols 32c+16pp+8ntl+2m+e at
// component 2*ntl+e. A quad (m=0..3) reads 64B contiguous.
__device__ float4 g_GIT3[2][NSYM][6][4];
__device__ float g_H1[NSYM * DD];          // GRU state after step 1 (key b0)
__device__ float g_H2[NSYM * NSYM * DD];   // GRU state after 2 steps, key (b0,b1)
// W_hh B fragments under the k-permutation pi(b, p) = 8b + 2p (p<4) /
// 8b + 2(p-4) + 1 (p>=4). This makes the A fragment of the next step equal
// to the lane's OWN C fragment (no shuffles).
__device__ float4 g_Bfrag[12][2][32];
__device__ float  g_bhn[DD];               // b_hh[64..95] (n-gate hidden bias)
__device__ float  g_wlr[DD];               // tf32-rounded w_lin

// ---------------------------------------------------------------------------
// TF32 emulation (reference matmuls are TF32 tensor-core GEMMs)
// ---------------------------------------------------------------------------
__device__ __forceinline__ float tf32r(float x) {
    float r;
    asm("cvt.rna.tf32.f32 %0, %1;" : "=f"(r) : "f"(x));
    return r;
}

// MUFU-native activations (abs err ~1e-5, proven negligible vs TF32 floor)
__device__ __forceinline__ float tanh_mufu(float x) {
    float r;
    asm("tanh.approx.f32 %0, %1;" : "=f"(r) : "f"(x));
    return r;
}
__device__ __forceinline__ float sig_mufu(float x) {
    return fmaf(0.5f, tanh_mufu(0.5f * x), 0.5f);
}

// tf32 MMA: D(16x8) += A(16x8) * B(8x8), fp32 accumulate
__device__ __forceinline__ void mma8(float c[4], const u32 a[4], u32 b0, u32 b1) {
    asm volatile(
        "mma.sync.aligned.m16n8k8.row.col.f32.tf32.tf32.f32 "
        "{%0,%1,%2,%3}, {%4,%5,%6,%7}, {%8,%9}, {%0,%1,%2,%3};"
        : "+f"(c[0]), "+f"(c[1]), "+f"(c[2]), "+f"(c[3])
        : "r"(a[0]), "r"(a[1]), "r"(a[2]), "r"(a[3]), "r"(b0), "r"(b1));
}

// ---------------------------------------------------------------------------
// One MMA GRU step on NT m16-tiles (16*NT paths/warp), shuffle-free:
// under the k-permutation, A fragments are the lane's own C fragments.
// gp0/gp1 = per-tile GIT3 base pointers (&GIT3[tab][sym][0][m]).
// ---------------------------------------------------------------------------
template<int NT>
__device__ __forceinline__ void gru_step_mma(
        float (*h_c)[4][4],
        const float4* const* gp0, const float4* const* gp1,
        const float4 (*sB)[2][32], const float* __restrict__ sBhn,
        int lane, int m) {
    // A fragments: a0=(grp, pos m)=h_c[b][0], a1=(grp+8, m)=h_c[b][2],
    //              a2=(grp, m+4)=h_c[b][1], a3=(grp+8, m+4)=h_c[b][3]
    u32 Ah[NT][4][4];
    #pragma unroll
    for (int tt = 0; tt < NT; tt++) {
        #pragma unroll
        for (int b = 0; b < 4; b++) {
            Ah[tt][b][0] = __float_as_uint(tf32r(h_c[tt][b][0]));
            Ah[tt][b][1] = __float_as_uint(tf32r(h_c[tt][b][2]));
            Ah[tt][b][2] = __float_as_uint(tf32r(h_c[tt][b][1]));
            Ah[tt][b][3] = __float_as_uint(tf32r(h_c[tt][b][3]));
        }
    }

    float rn[NT][4][4];   // r, then n in place

    // --- r gates (GIT3 slots 0..1, B frags 0..3): c init = gi_r+b_ih+b_hh ---
    #pragma unroll
    for (int pp = 0; pp < 2; pp++) {
        float ci[NT][2][4];
        #pragma unroll
        for (int tt = 0; tt < NT; tt++) {
            float4 ga = __ldg(gp0[tt] + 4 * pp);
            float4 gb = __ldg(gp1[tt] + 4 * pp);
            ci[tt][0][0] = ga.x; ci[tt][0][1] = ga.y; ci[tt][0][2] = gb.x; ci[tt][0][3] = gb.y;
            ci[tt][1][0] = ga.z; ci[tt][1][1] = ga.w; ci[tt][1][2] = gb.z; ci[tt][1][3] = gb.w;
        }
        #pragma unroll
        for (int ntl = 0; ntl < 2; ntl++) {
            int nt = 2 * pp + ntl;
            float4 b0 = sB[nt][0][lane];
            float4 b1 = sB[nt][1][lane];
            #pragma unroll
            for (int tt = 0; tt < NT; tt++) {
                mma8(ci[tt][ntl], Ah[tt][0], __float_as_uint(b0.x), __float_as_uint(b0.y));
                mma8(ci[tt][ntl], Ah[tt][1], __float_as_uint(b0.z), __float_as_uint(b0.w));
                mma8(ci[tt][ntl], Ah[tt][2], __float_as_uint(b1.x), __float_as_uint(b1.y));
                mma8(ci[tt][ntl], Ah[tt][3], __float_as_uint(b1.z), __float_as_uint(b1.w));
                rn[tt][nt][0] = sig_mufu(ci[tt][ntl][0]);
                rn[tt][nt][1] = sig_mufu(ci[tt][ntl][1]);
                rn[tt][nt][2] = sig_mufu(ci[tt][ntl][2]);
                rn[tt][nt][3] = sig_mufu(ci[tt][ntl][3]);
            }
        }
    }

    // --- n gates (GIT3 slots 4..5, B frags 8..11): n = tanh(r*gh_n + gi_n) ---
    #pragma unroll
    for (int pp = 0; pp < 2; pp++) {
        float gi0[NT][4], gi1[NT][4];
        #pragma unroll
        for (int tt = 0; tt < NT; tt++) {
            float4 ga = __ldg(gp0[tt] + 16 + 4 * pp);
            float4 gb = __ldg(gp1[tt] + 16 + 4 * pp);
            gi0[tt][0] = ga.x; gi0[tt][1] = ga.y; gi0[tt][2] = gb.x; gi0[tt][3] = gb.y;
            gi1[tt][0] = ga.z; gi1[tt][1] = ga.w; gi1[tt][2] = gb.z; gi1[tt][3] = gb.w;
        }
        #pragma unroll
        for (int ntl = 0; ntl < 2; ntl++) {
            int nt = 2 * pp + ntl;
            float2 bb = *(const float2*)&sBhn[8 * nt + 2 * m];
            float4 b0 = sB[8 + nt][0][lane];
            float4 b1 = sB[8 + nt][1][lane];
            #pragma unroll
            for (int tt = 0; tt < NT; tt++) {
                float ch[4] = {bb.x, bb.y, bb.x, bb.y};
                mma8(ch, Ah[tt][0], __float_as_uint(b0.x), __float_as_uint(b0.y));
                mma8(ch, Ah[tt][1], __float_as_uint(b0.z), __float_as_uint(b0.w));
                mma8(ch, Ah[tt][2], __float_as_uint(b1.x), __float_as_uint(b1.y));
                mma8(ch, Ah[tt][3], __float_as_uint(b1.z), __float_as_uint(b1.w));
                const float* gi = ntl ? gi1[tt] : gi0[tt];
                rn[tt][nt][0] = tanh_mufu(fmaf(rn[tt][nt][0], ch[0], gi[0]));
                rn[tt][nt][1] = tanh_mufu(fmaf(rn[tt][nt][1], ch[1], gi[1]));
                rn[tt][nt][2] = tanh_mufu(fmaf(rn[tt][nt][2], ch[2], gi[2]));
                rn[tt][nt][3] = tanh_mufu(fmaf(rn[tt][nt][3], ch[3], gi[3]));
            }
        }
    }

    // --- z gates (GIT3 slots 2..3, B frags 4..7) + update h = n + z*(h-n) ---
    #pragma unroll
    for (int pp = 0; pp < 2; pp++) {
        float ci[NT][2][4];
        #pragma unroll
        for (int tt = 0; tt < NT; tt++) {
            float4 ga = __ldg(gp0[tt] + 8 + 4 * pp);
            float4 gb = __ldg(gp1[tt] + 8 + 4 * pp);
            ci[tt][0][0] = ga.x; ci[tt][0][1] = ga.y; ci[tt][0][2] = gb.x; ci[tt][0][3] = gb.y;
            ci[tt][1][0] = ga.z; ci[tt][1][1] = ga.w; ci[tt][1][2] = gb.z; ci[tt][1][3] = gb.w;
        }
        #pragma unroll
        for (int ntl = 0; ntl < 2; ntl++) {
            int nt = 2 * pp + ntl;
            float4 b0 = sB[4 + nt][0][lane];
            float4 b1 = sB[4 + nt][1][lane];
            #pragma unroll
            for (int tt = 0; tt < NT; tt++) {
                mma8(ci[tt][ntl], Ah[tt][0], __float_as_uint(b0.x), __float_as_uint(b0.y));
                mma8(ci[tt][ntl], Ah[tt][1], __float_as_uint(b0.z), __float_as_uint(b0.w));
                mma8(ci[tt][ntl], Ah[tt][2], __float_as_uint(b1.x), __float_as_uint(b1.y));
                mma8(ci[tt][ntl], Ah[tt][3], __float_as_uint(b1.z), __float_as_uint(b1.w));
                #pragma unroll
                for (int e = 0; e < 4; e++) {
                    float z = sig_mufu(ci[tt][ntl][e]);
                    float n = rn[tt][nt][e];
                    h_c[tt][nt][e] = fmaf(z, h_c[tt][nt][e] - n, n);
                }
            }
        }
    }
}

// ---------------------------------------------------------------------------
// K_setup: fused zero + GIT/GIT3 + Bfrag(W_hh, permuted) + b_hh_n + w_lin.
// ---------------------------------------------------------------------------
__global__ void k_setup(float* out, int out_size,
                        const float* __restrict__ all_emb,
                        const float* __restrict__ edge_emb,
                        const float* __restrict__ w_ih,
                        const float* __restrict__ w_hh,
                        const float* __restrict__ b_ih,
                        const float* __restrict__ b_hh,
                        const float* __restrict__ w_lin) {
    int i = blockIdx.x * blockDim.x + threadIdx.x;
    if (i < 1024) {
        for (int k = i; k < out_size; k += 1024) out[k] = 0.0f;
        return;
    }
    int g = i - 1024;
    if (g < 12288) {               // GIT: TF32 products, fp64 sum, biases folded
        int tab = g / 6144, rem = g % 6144;
        int sym = rem / GI_W, j = rem % GI_W;
        const float* x = tab ? (edge_emb + sym * DD) : (all_emb + sym * DD);
        const float* w = w_ih + j * DD;
        double acc = 0.0;
        #pragma unroll
        for (int k = 0; k < DD; k++)
            acc += (double)tf32r(__ldg(w + k)) * (double)tf32r(__ldg(x + k));
        acc += (double)__ldg(b_ih + j);
        if (j < 64) acc += (double)__ldg(b_hh + j);   // fold b_hh for r/z gates
        float v = (float)acc;
        g_GIT[tab][sym][j] = v;
        // slot-major copy: col j = 32c + 16pp + 8ntl + 2m + e
        //   -> GIT3[tab][sym][2c+pp][m] component 2*ntl+e
        int c = j >> 5, r5 = j & 31;
        int pp = r5 >> 4, r4 = r5 & 15;
        int ntl = r4 >> 3, r3 = r4 & 7;
        int mm = r3 >> 1, e = r3 & 1;
        float* dst = (float*)&g_GIT3[tab][sym][0][0];
        dst[((2 * c + pp) * 4 + mm) * 4 + 2 * ntl + e] = v;
        return;
    }
    int j = i - 13312;
    if (j >= 0 && j < 768) {       // W_hh B fragments with pi permutation:
        int lane = j & 31;         //   block b, pos p<4 -> col 8b+2p; p>=4 -> 8b+2(p-4)+1
        int r1 = j >> 5;           // 0..23
        int kp = r1 & 1;
        int nt = r1 >> 1;          // 0..11
        int row = 8 * nt + (lane >> 2);
        int q = lane & 3;
        g_Bfrag[nt][kp][lane] = make_float4(
            tf32r(w_hh[row * DD + 16 * kp + 2 * q]),
            tf32r(w_hh[row * DD + 16 * kp + 2 * q + 1]),
            tf32r(w_hh[row * DD + 16 * kp + 8 + 2 * q]),
            tf32r(w_hh[row * DD + 16 * kp + 8 + 2 * q + 1]));
        return;
    }
    int k = i - 14080;
    if (k >= 0 && k < DD) { g_bhn[k] = b_hh[64 + k]; return; }
    int w = i - 14112;
    if (w >= 0 && w < DD) g_wlr[w] = tf32r(w_lin[w]);
}

// ---------------------------------------------------------------------------
// K_h1: step 1 from h0=0 — depends only on b0 (elementwise; biases pre-folded)
// ---------------------------------------------------------------------------
__global__ void k_h1(int dummy) {
    int i = blockIdx.x * blockDim.x + threadIdx.x;
    if (i >= NSYM * DD) return;
    int e0 = i >> 5, j = i & 31;
    const float* git = &g_GIT[0][e0][0];
    float r = sig_mufu(git[j]);
    float z = sig_mufu(git[32 + j]);
    float n = tanh_mufu(fmaf(r, g_bhn[j], git[64 + j]));
    g_H1[e0 * DD + j] = (1.0f - z) * n;
}

// ---------------------------------------------------------------------------
// K_h2: H2 table via MMA (NT=1). One warp = 16 consecutive keys.
// ---------------------------------------------------------------------------
__global__ void __launch_bounds__(128) k_h2(int dummy) {
    __shared__ float4 sB[12][2][32];
    __shared__ float sBhn[DD];
    int tid = threadIdx.x;
    {
        const float4* src = &g_Bfrag[0][0][0];
        float4* dst = &sB[0][0][0];
        for (int i = tid; i < 768; i += 128) dst[i] = src[i];
        if (tid < DD) sBhn[tid] = g_bhn[tid];
    }
    __syncthreads();

    int warp = tid >> 5, lane = tid & 31;
    int m = lane & 3, grp = lane >> 2;

    int kbase = (blockIdx.x * 4 + warp) * 16;
    int key0 = kbase + grp;
    int key1 = key0 + 8;

    float h_c[1][4][4];
    const float* H0 = g_H1 + (key0 >> 6) * DD;
    const float* H1 = g_H1 + (key1 >> 6) * DD;
    #pragma unroll
    for (int nt = 0; nt < 4; nt++) {
        float2 v0 = *(const float2*)(H0 + 8 * nt + 2 * m);
        float2 v1 = *(const float2*)(H1 + 8 * nt + 2 * m);
        h_c[0][nt][0] = v0.x; h_c[0][nt][1] = v0.y;
        h_c[0][nt][2] = v1.x; h_c[0][nt][3] = v1.y;
    }

    const float4* gp0[1] = { &g_GIT3[1][key0 & 63][0][m] };
    const float4* gp1[1] = { &g_GIT3[1][key1 & 63][0][m] };
    gru_step_mma<1>(h_c, gp0, gp1, sB, sBhn, lane, m);

    float* D0 = g_H2 + key0 * DD;
    float* D1 = g_H2 + key1 * DD;
    #pragma unroll
    for (int nt = 0; nt < 4; nt++) {
        *(float2*)(D0 + 8 * nt + 2 * m) = make_float2(h_c[0][nt][0], h_c[0][nt][1]);
        *(float2*)(D1 + 8 * nt + 2 * m) = make_float2(h_c[0][nt][2], h_c[0][nt][3]);
    }
}

// ---------------------------------------------------------------------------
// K_main: one warp = 32 paths (2 m16 tiles share every B-fragment LDS).
// ---------------------------------------------------------------------------
__global__ void __launch_bounds__(128, 3) k_main(
        const int* __restrict__ path, const int* __restrict__ path_idx,
        const float* __restrict__ b_lin, float* __restrict__ out, int n_paths) {
    __shared__ float4 sB[12][2][32];
    __shared__ float sBhn[DD];
    __shared__ float sWl[DD];

    int tid = threadIdx.x;
    {
        const float4* src = &g_Bfrag[0][0][0];
        float4* dst = &sB[0][0][0];
        for (int i = tid; i < 768; i += 128) dst[i] = src[i];
        if (tid < DD) sBhn[tid] = g_bhn[tid];
        if (tid >= 64 && tid < 64 + DD) sWl[tid - 64] = g_wlr[tid - 64];
    }
    __syncthreads();

    int lane = tid & 31;
    int m = lane & 3, grp = lane >> 2;

    int pbase = (blockIdx.x * 4 + (tid >> 5)) * 32;
    int n1 = n_paths - 1;

    // Load per-tile symbols (packed) and H2 state
    int spk[2][2];                 // [tile][half]: b2 | b3<<8 | b4<<16
    float h_c[2][4][4];
    #pragma unroll
    for (int tt = 0; tt < 2; tt++) {
        #pragma unroll
        for (int hf = 0; hf < 2; hf++) {
            int p = min(pbase + 16 * tt + grp + 8 * hf, n1);
            const int* P = path + p * 5;
            int b0 = __ldg(P + 0), b1 = __ldg(P + 1);
            spk[tt][hf] = __ldg(P + 2) | (__ldg(P + 3) << 8) | (__ldg(P + 4) << 16);
            const float* H = g_H2 + (b0 * NSYM + b1) * DD;
            #pragma unroll
            for (int nt = 0; nt < 4; nt++) {
                float2 v = *(const float2*)(H + 8 * nt + 2 * m);
                h_c[tt][nt][2 * hf + 0] = v.x;
                h_c[tt][nt][2 * hf + 1] = v.y;
            }
        }
    }

    #pragma unroll 1
    for (int t = 0; t < 3; t++) {
        int tab = (t == 1) ? 1 : 0;
        int sh = 8 * t;
        const float4* gp0[2] = {
            &g_GIT3[tab][(spk[0][0] >> sh) & 63][0][m],
            &g_GIT3[tab][(spk[1][0] >> sh) & 63][0][m] };
        const float4* gp1[2] = {
            &g_GIT3[tab][(spk[0][1] >> sh) & 63][0][m],
            &g_GIT3[tab][(spk[1][1] >> sh) & 63][0][m] };
        gru_step_mma<2>(h_c, gp0, gp1, sB, sBhn, lane, m);
    }

    // Head: s = tf32(h) . tf32(w_lin) + b_lin, quad-reduced per tile
    float bl = __ldg(b_lin);
    #pragma unroll
    for (int tt = 0; tt < 2; tt++) {
        float sc0 = 0.0f, sc1 = 0.0f;
        #pragma unroll
        for (int nt = 0; nt < 4; nt++) {
            float2 wl = *(const float2*)&sWl[8 * nt + 2 * m];
            sc0 = fmaf(tf32r(h_c[tt][nt][0]), wl.x, sc0);
            sc0 = fmaf(tf32r(h_c[tt][nt][1]), wl.y, sc0);
            sc1 = fmaf(tf32r(h_c[tt][nt][2]), wl.x, sc1);
            sc1 = fmaf(tf32r(h_c[tt][nt][3]), wl.y, sc1);
        }
        sc0 += __shfl_xor_sync(0xffffffffu, sc0, 1);
        sc0 += __shfl_xor_sync(0xffffffffu, sc0, 2);
        sc1 += __shfl_xor_sync(0xffffffffu, sc1, 1);
        sc1 += __shfl_xor_sync(0xffffffffu, sc1, 2);
        if (m == 0) {
            int p0 = pbase + 16 * tt + grp;
            int p1 = p0 + 8;
            if (p0 < n_paths) atomicAdd(out + __ldg(path_idx + p0), sc0 + bl);
            if (p1 < n_paths) atomicAdd(out + __ldg(path_idx + p1), sc1 + bl);
        }
    }
}

// ---------------------------------------------------------------------------
extern "C" void kernel_launch(void* const* d_in, const int* in_sizes, int n_in,
                              void* d_out, int out_size) {
    // inputs: 0 users, 1 path, 2 path_idx, 3 all_emb, 4 edge_emb, 5 virtual_emb,
    //         6 w_ih, 7 w_hh, 8 b_ih, 9 b_hh, 10 w_lin, 11 b_lin
    const int*   path     = (const int*)d_in[1];
    const int*   path_idx = (const int*)d_in[2];
    const float* all_emb  = (const float*)d_in[3];
    const float* edge_emb = (const float*)d_in[4];
    const float* w_ih     = (const float*)d_in[6];
    const float* w_hh     = (const float*)d_in[7];
    const float* b_ih     = (const float*)d_in[8];
    const float* b_hh     = (const float*)d_in[9];
    const float* w_lin    = (const float*)d_in[10];
    const float* b_lin    = (const float*)d_in[11];
    float* out = (float*)d_out;
    int n_paths = in_sizes[2];

    k_setup<<<56, 256>>>(out, out_size, all_emb, edge_emb, w_ih, w_hh,
                         b_ih, b_hh, w_lin);
    k_h1<<<2, 1024>>>(0);
    k_h2<<<64, 128>>>(0);
    int nblocks = (n_paths + 127) / 128;   // 128 paths per block (4 warps x 32)
    k_main<<<nblocks, 128>>>(path, path_idx, b_lin, out, n_paths);
}